// round 17
// baseline (speedup 1.0000x reference)
#include <cuda_runtime.h>
#include <cuda_fp16.h>
#include <math.h>
#include <stdint.h>

// ---------------- problem dims ----------------
#define B_   4
#define L_   2048
#define DM_  1024
#define DS_  16
#define DC_  4
#define DI_  2048
#define N1_  4096              // 2*DI
#define M_   (B_ * L_)         // 8192
#define NC_  64                // padded N for the dbc GEMM (49 used)
#define KZ_  2                 // K-split for dbc

// ---------------- scratch (__device__ globals, no allocation) ----------------
__device__ __half g_xinner[(size_t)M_ * N1_];    // fp16
__device__ __half g_xc16  [(size_t)M_ * DI_];    // fp16 x_conv
__device__ float g_dots  [(size_t)KZ_ * M_ * NC_];  // partial dots
__device__ float g_hc[M_ * DS_];   // h*C, s-major
__device__ __half g_xf [(size_t)M_  * DM_];
__device__ __half g_w1 [(size_t)N1_ * DM_];
__device__ __half g_wo [(size_t)DM_ * DI_];
__device__ __half g_wc [(size_t)NC_ * DI_];      // [deltaw;Bw;Cw;ones;0...]
__device__ __half g_ys [(size_t)M_  * DI_];

// ---------------- helpers ----------------
__device__ __forceinline__ uint32_t smem_u32(const void* p) {
    uint32_t a;
    asm("{ .reg .u64 t; cvta.to.shared.u64 t, %1; cvt.u32.u64 %0, t; }" : "=r"(a) : "l"(p));
    return a;
}
__device__ __forceinline__ void cp16(uint32_t dst, const void* src) {
    asm volatile("cp.async.cg.shared.global [%0], [%1], 16;" :: "r"(dst), "l"(src));
}
__device__ __forceinline__ void cp_commit() {
    asm volatile("cp.async.commit_group;" ::: "memory");
}
__device__ __forceinline__ void cp_wait1() {
    asm volatile("cp.async.wait_group 1;" ::: "memory");
}
__device__ __forceinline__ void ldm_x4(uint32_t* r, uint32_t addr) {
    asm volatile("ldmatrix.sync.aligned.m8n8.x4.shared.b16 {%0,%1,%2,%3}, [%4];"
        : "=r"(r[0]), "=r"(r[1]), "=r"(r[2]), "=r"(r[3]) : "r"(addr));
}
__device__ __forceinline__ void mma_fp16(float* c, const uint32_t* a, const uint32_t* b) {
    asm volatile(
        "mma.sync.aligned.m16n8k16.row.col.f32.f16.f16.f32 "
        "{%0,%1,%2,%3}, {%4,%5,%6,%7}, {%8,%9}, {%0,%1,%2,%3};"
        : "+f"(c[0]), "+f"(c[1]), "+f"(c[2]), "+f"(c[3])
        : "r"(a[0]), "r"(a[1]), "r"(a[2]), "r"(a[3]), "r"(b[0]), "r"(b[1]));
}
__device__ __forceinline__ float fast_sigmoid(float v) {
    return 1.f / (1.f + __expf(-v));
}

// ---------------- HMMA fp16 GEMM: C[M,*] = A[M,K] @ W[*,K]^T ----------------
#define BM 128
#define BN 128
#define BK 64
#define LDS_ROW 72
#define TILE_B (128 * LDS_ROW * 2)
#define STAGE_B (2 * TILE_B)
#define STAGES 3
#define SMEM_TOTAL (STAGES * STAGE_B)    // 110592

__device__ __forceinline__ void stage_load(uint32_t sbase,
    const __half* __restrict__ A, const __half* __restrict__ W,
    int k0, int lda, int tid)
{
    const __half* srcs[2] = {A, W};
    #pragma unroll
    for (int a = 0; a < 2; a++) {
        #pragma unroll
        for (int i = 0; i < 4; i++) {
            int idx = i * 256 + tid;
            int row = idx >> 3;
            int c8  = (idx & 7) * 8;
            cp16(sbase + a * TILE_B + row * (LDS_ROW * 2) + c8 * 2,
                 srcs[a] + (size_t)row * lda + k0 + c8);
        }
    }
}

template <typename TOut>
__global__ __launch_bounds__(256, 2) void gemm_tc(
    const __half* __restrict__ A, const __half* __restrict__ W,
    TOut* __restrict__ C, int M, int ldc, int lda, int Kchunk)
{
    extern __shared__ char smem[];
    uint32_t sb = smem_u32(smem);
    const int tid = threadIdx.x, wid = tid >> 5, lane = tid & 31;
    const int wm = wid >> 2, wn = wid & 3;
    const int m0 = blockIdx.y * BM, n0 = blockIdx.x * BN;

    const __half* Ap = A + (size_t)m0 * lda;
    const __half* Wp = W + (size_t)n0 * lda;

    float acc[4][4][4];
    #pragma unroll
    for (int i = 0; i < 4; i++)
        #pragma unroll
        for (int j = 0; j < 4; j++)
            #pragma unroll
            for (int q = 0; q < 4; q++) acc[i][j][q] = 0.f;

    const int T = Kchunk / BK;
    stage_load(sb + 0 * STAGE_B, Ap, Wp, 0, lda, tid);
    cp_commit();
    stage_load(sb + 1 * STAGE_B, Ap, Wp, BK, lda, tid);
    cp_commit();

    const int l15 = lane & 15;
    const int a_khalf = (lane >> 4) & 1;
    const int b_grp = lane >> 3, b_r = lane & 7;
    const int b_row_off = ((b_grp >> 1) << 3) + b_r;
    const int b_kb = (b_grp & 1) * 16;

    for (int t = 0; t < T; t++) {
        cp_wait1();
        __syncthreads();
        if (t + 2 < T)
            stage_load(sb + ((t + 2) % STAGES) * STAGE_B, Ap, Wp,
                       (t + 2) * BK, lda, tid);
        cp_commit();

        uint32_t cur = sb + (t % STAGES) * STAGE_B;
        #pragma unroll
        for (int kk = 0; kk < 4; kk++) {
            uint32_t af[4][4], wf[2][4];
            #pragma unroll
            for (int mi = 0; mi < 4; mi++) {
                int row = wm * 64 + mi * 16 + l15;
                ldm_x4(af[mi], cur + row * (LDS_ROW * 2) + kk * 32 + a_khalf * 16);
            }
            #pragma unroll
            for (int n2 = 0; n2 < 2; n2++) {
                int row = wn * 32 + n2 * 16 + b_row_off;
                ldm_x4(wf[n2], cur + TILE_B + row * (LDS_ROW * 2) + kk * 32 + b_kb);
            }
            #pragma unroll
            for (int mi = 0; mi < 4; mi++)
                #pragma unroll
                for (int ni = 0; ni < 4; ni++)
                    mma_fp16(acc[mi][ni], af[mi], &wf[ni >> 1][(ni & 1) * 2]);
        }
    }

    const int g = lane >> 2, tq = lane & 3;
    #pragma unroll
    for (int mi = 0; mi < 4; mi++) {
        #pragma unroll
        for (int ni = 0; ni < 4; ni++) {
            int row = m0 + wm * 64 + mi * 16 + g;
            int col = n0 + wn * 32 + ni * 8 + tq * 2;
            if (sizeof(TOut) == 4) {
                *(float2*)((float*)C + (size_t)row * ldc + col) =
                    make_float2(acc[mi][ni][0], acc[mi][ni][1]);
                *(float2*)((float*)C + (size_t)(row + 8) * ldc + col) =
                    make_float2(acc[mi][ni][2], acc[mi][ni][3]);
            } else {
                __half2 h0 = __floats2half2_rn(acc[mi][ni][0], acc[mi][ni][1]);
                __half2 h1 = __floats2half2_rn(acc[mi][ni][2], acc[mi][ni][3]);
                *(uint32_t*)((__half*)C + (size_t)row * ldc + col) = *(uint32_t*)&h0;
                *(uint32_t*)((__half*)C + (size_t)(row + 8) * ldc + col) = *(uint32_t*)&h1;
            }
        }
    }
}

// ============ fused conv+silu+dbc GEMM ======================================
// Grid (1, M/64, KZ). Each CTA: 64 m-rows x (DI/KZ) K-chunk.
// A tile (64x64 x_conv fp16) produced in-kernel from g_xinner (conv+silu),
// stored to smem (MMA operand) AND g_xc16 (for yskip). W via cp.async.
#define CD_ABUF  (64 * LDS_ROW * 2)            // 9216
#define CD_A_OFF 0
#define CD_W_OFF (2 * CD_ABUF)                 // 18432
#define CD_CW_OFF (CD_W_OFF + 3 * CD_ABUF)     // 46080
#define CD_CB_OFF (CD_CW_OFF + 2048)           // 48128
#define CD_SMEM  (CD_CB_OFF + 512)             // 48640

__global__ __launch_bounds__(256, 2) void convdbc_kernel(
    const __half* __restrict__ Wc,
    const float* __restrict__ cw, const float* __restrict__ cb,
    float* __restrict__ Cdots, int Kchunk)
{
    extern __shared__ char smem[];
    uint32_t sb = smem_u32(smem);
    const int tid = threadIdx.x, wid = tid >> 5, lane = tid & 31;
    const int wm = wid >> 2, wn = wid & 3;        // 2m x 4n, warp 32x16
    const int m0 = blockIdx.y * 64;
    const int zbase = blockIdx.z * Kchunk;
    float* Cp = Cdots + (size_t)blockIdx.z * M_ * NC_;

    // producer mapping: 16 row-groups (4 rows) x 16 channel-quads
    const int rg = tid >> 4;
    const int cq = tid & 15;
    const int c0 = cq * 4;
    const int gr0 = m0 + rg * 4;
    const int l0 = gr0 & (L_ - 1);

    const int T = Kchunk / BK;
    const __half* Wp = Wc + zbase;

    float acc[2][2][4];
    #pragma unroll
    for (int i = 0; i < 2; i++)
        #pragma unroll
        for (int j = 0; j < 2; j++)
            #pragma unroll
            for (int q = 0; q < 4; q++) acc[i][j][q] = 0.f;

    // ---- prologue ----
    // conv weights for ktile 0 -> wbuf 0
    if (tid < 64) {
        int ch = zbase + tid;
        *(float4*)(smem + CD_CW_OFF + 0 * 1024 + tid * 16) = *(const float4*)(cw + ch * 4);
        *(float*)(smem + CD_CB_OFF + 0 * 256 + tid * 4) = cb[ch];
    }
    // W cp.async stages 0,1
    #pragma unroll
    for (int p = 0; p < 2; p++) {
        #pragma unroll
        for (int i = 0; i < 2; i++) {
            int idx = i * 256 + tid;
            int row = idx >> 3;
            int c8  = (idx & 7) * 8;
            cp16(sb + CD_W_OFF + p * CD_ABUF + row * (LDS_ROW * 2) + c8 * 2,
                 Wp + (size_t)row * DI_ + p * BK + c8);
        }
        cp_commit();
    }
    __syncthreads();   // conv weights(0) visible

    uint2 q[7];
    // taps for ktile 0
    {
        int kcol = zbase;
        #pragma unroll
        for (int j = 0; j < 7; j++) {
            if (l0 - 3 + j >= 0)
                q[j] = *(const uint2*)(g_xinner + (size_t)(gr0 - 3 + j) * N1_ + kcol + c0);
            else
                q[j] = make_uint2(0u, 0u);
        }
    }
    // produce A(0) into abuf 0 (+ gmem)
    {
        int kcol = zbase;
        float w[4][4], bias[4];
        #pragma unroll
        for (int c = 0; c < 4; c++) {
            float4 t4 = *(float4*)(smem + CD_CW_OFF + 0 * 1024 + (c0 + c) * 16);
            w[c][0] = t4.x; w[c][1] = t4.y; w[c][2] = t4.z; w[c][3] = t4.w;
            bias[c] = *(float*)(smem + CD_CB_OFF + 0 * 256 + (c0 + c) * 4);
        }
        #pragma unroll
        for (int rr = 0; rr < 4; rr++) {
            float a[4] = {bias[0], bias[1], bias[2], bias[3]};
            #pragma unroll
            for (int k = 0; k < 4; k++) {
                uint2 v = q[rr + k];
                float2 f0 = __half22float2(*(__half2*)&v.x);
                float2 f1 = __half22float2(*(__half2*)&v.y);
                a[0] = fmaf(f0.x, w[0][k], a[0]);
                a[1] = fmaf(f0.y, w[1][k], a[1]);
                a[2] = fmaf(f1.x, w[2][k], a[2]);
                a[3] = fmaf(f1.y, w[3][k], a[3]);
            }
            float s0 = a[0] * fast_sigmoid(a[0]);
            float s1 = a[1] * fast_sigmoid(a[1]);
            float s2 = a[2] * fast_sigmoid(a[2]);
            float s3 = a[3] * fast_sigmoid(a[3]);
            __half2 h0 = __floats2half2_rn(s0, s1);
            __half2 h1 = __floats2half2_rn(s2, s3);
            uint2 pk = make_uint2(*(uint32_t*)&h0, *(uint32_t*)&h1);
            *(uint2*)(smem + CD_A_OFF + 0 * CD_ABUF + (rg * 4 + rr) * (LDS_ROW * 2) + c0 * 2) = pk;
            *(uint2*)(g_xc16 + (size_t)(gr0 + rr) * DI_ + kcol + c0) = pk;
        }
    }

    const int l15 = lane & 15;
    const int a_khalf = (lane >> 4) & 1;
    const int b_grp = lane >> 3, b_r = lane & 7;
    const int b_row_off = ((b_grp >> 1) << 3) + b_r;
    const int b_kb = (b_grp & 1) * 16;

    for (int t = 0; t < T; t++) {
        const int tn = t + 1;
        // early: taps(t+1) + conv weights(t+1) STS (before barrier)
        if (tn < T) {
            int kcol = zbase + tn * BK;
            #pragma unroll
            for (int j = 0; j < 7; j++) {
                if (l0 - 3 + j >= 0)
                    q[j] = *(const uint2*)(g_xinner + (size_t)(gr0 - 3 + j) * N1_ + kcol + c0);
                else
                    q[j] = make_uint2(0u, 0u);
            }
            if (tid < 64) {
                int ch = kcol + tid;
                *(float4*)(smem + CD_CW_OFF + (tn & 1) * 1024 + tid * 16) = *(const float4*)(cw + ch * 4);
                *(float*)(smem + CD_CB_OFF + (tn & 1) * 256 + tid * 4) = cb[ch];
            }
        }
        cp_wait1();
        __syncthreads();
        if (t + 2 < T) {
            #pragma unroll
            for (int i = 0; i < 2; i++) {
                int idx = i * 256 + tid;
                int row = idx >> 3;
                int c8  = (idx & 7) * 8;
                cp16(sb + CD_W_OFF + ((t + 2) % 3) * CD_ABUF + row * (LDS_ROW * 2) + c8 * 2,
                     Wp + (size_t)row * DI_ + (t + 2) * BK + c8);
            }
        }
        cp_commit();

        // MMA on A buf (t&1), W stage (t%3)
        uint32_t curA = sb + CD_A_OFF + (t & 1) * CD_ABUF;
        uint32_t curW = sb + CD_W_OFF + (t % 3) * CD_ABUF;
        #pragma unroll
        for (int kk = 0; kk < 4; kk++) {
            uint32_t af[2][4], wf[4];
            #pragma unroll
            for (int mi = 0; mi < 2; mi++) {
                int row = wm * 32 + mi * 16 + l15;
                ldm_x4(af[mi], curA + row * (LDS_ROW * 2) + kk * 32 + a_khalf * 16);
            }
            {
                int row = wn * 16 + b_row_off;
                ldm_x4(wf, curW + row * (LDS_ROW * 2) + kk * 32 + b_kb);
            }
            #pragma unroll
            for (int mi = 0; mi < 2; mi++)
                #pragma unroll
                for (int ni = 0; ni < 2; ni++)
                    mma_fp16(acc[mi][ni], af[mi], &wf[ni * 2]);
        }

        // produce A(t+1)
        if (tn < T) {
            int kcol = zbase + tn * BK;
            int wb = tn & 1;
            float w[4][4], bias[4];
            #pragma unroll
            for (int c = 0; c < 4; c++) {
                float4 t4 = *(float4*)(smem + CD_CW_OFF + wb * 1024 + (c0 + c) * 16);
                w[c][0] = t4.x; w[c][1] = t4.y; w[c][2] = t4.z; w[c][3] = t4.w;
                bias[c] = *(float*)(smem + CD_CB_OFF + wb * 256 + (c0 + c) * 4);
            }
            #pragma unroll
            for (int rr = 0; rr < 4; rr++) {
                float a[4] = {bias[0], bias[1], bias[2], bias[3]};
                #pragma unroll
                for (int k = 0; k < 4; k++) {
                    uint2 v = q[rr + k];
                    float2 f0 = __half22float2(*(__half2*)&v.x);
                    float2 f1 = __half22float2(*(__half2*)&v.y);
                    a[0] = fmaf(f0.x, w[0][k], a[0]);
                    a[1] = fmaf(f0.y, w[1][k], a[1]);
                    a[2] = fmaf(f1.x, w[2][k], a[2]);
                    a[3] = fmaf(f1.y, w[3][k], a[3]);
                }
                float s0 = a[0] * fast_sigmoid(a[0]);
                float s1 = a[1] * fast_sigmoid(a[1]);
                float s2 = a[2] * fast_sigmoid(a[2]);
                float s3 = a[3] * fast_sigmoid(a[3]);
                __half2 h0 = __floats2half2_rn(s0, s1);
                __half2 h1 = __floats2half2_rn(s2, s3);
                uint2 pk = make_uint2(*(uint32_t*)&h0, *(uint32_t*)&h1);
                *(uint2*)(smem + CD_A_OFF + (tn & 1) * CD_ABUF + (rg * 4 + rr) * (LDS_ROW * 2) + c0 * 2) = pk;
                *(uint2*)(g_xc16 + (size_t)(gr0 + rr) * DI_ + kcol + c0) = pk;
            }
        }
    }

    const int g = lane >> 2, tq = lane & 3;
    #pragma unroll
    for (int mi = 0; mi < 2; mi++) {
        #pragma unroll
        for (int ni = 0; ni < 2; ni++) {
            int row = m0 + wm * 32 + mi * 16 + g;
            int col = wn * 16 + ni * 8 + tq * 2;
            *(float2*)(Cp + (size_t)row * NC_ + col) =
                make_float2(acc[mi][ni][0], acc[mi][ni][1]);
            *(float2*)(Cp + (size_t)(row + 8) * NC_ + col) =
                make_float2(acc[mi][ni][2], acc[mi][ni][3]);
        }
    }
}

// ---------------- merged prep: cvt x | cvt w1 | cvt wo | build wcat --------
#define NB_X  (M_ * DM_ / 4 / 256)
#define NB_W1 (N1_ * DM_ / 4 / 256)
#define NB_WO (DM_ * DI_ / 4 / 256)
#define NB_WC (NC_ * DI_ / 4 / 256)
__global__ __launch_bounds__(256) void prep_all_kernel(
    const float* __restrict__ x, const float* __restrict__ w1,
    const float* __restrict__ wo,
    const float* __restrict__ dw, const float* __restrict__ bw,
    const float* __restrict__ cw)
{
    int blk = blockIdx.x;
    if (blk < NB_X + NB_W1 + NB_WO) {
        const float* src; __half* dst; int i;
        if (blk < NB_X) {
            src = x;  dst = g_xf;  i = blk * 256 + threadIdx.x;
        } else if (blk < NB_X + NB_W1) {
            src = w1; dst = g_w1;  i = (blk - NB_X) * 256 + threadIdx.x;
        } else {
            src = wo; dst = g_wo;  i = (blk - NB_X - NB_W1) * 256 + threadIdx.x;
        }
        float4 v = ((const float4*)src)[i];
        __half2 a = __floats2half2_rn(v.x, v.y);
        __half2 b = __floats2half2_rn(v.z, v.w);
        ((uint2*)dst)[i] = make_uint2(*(uint32_t*)&a, *(uint32_t*)&b);
    } else {
        int i = (blk - NB_X - NB_W1 - NB_WO) * 256 + threadIdx.x;
        int row = i / (DI_ / 4);
        int c4  = (i % (DI_ / 4)) * 4;
        float4 v;
        if (row < 16)       v = *(const float4*)(dw + (size_t)row * DI_ + c4);
        else if (row < 32)  v = *(const float4*)(bw + (size_t)(row - 16) * DI_ + c4);
        else if (row < 48)  v = *(const float4*)(cw + (size_t)(row - 32) * DI_ + c4);
        else if (row == 48) v = make_float4(1.f, 1.f, 1.f, 1.f);
        else                v = make_float4(0.f, 0.f, 0.f, 0.f);
        __half2 a = __floats2half2_rn(v.x, v.y);
        __half2 b = __floats2half2_rn(v.z, v.w);
        ((uint2*)g_wc)[i] = make_uint2(*(uint32_t*)&a, *(uint32_t*)&b);
    }
}

// ---------------- scan (gu fused): one block per (b,s), 128 threads ---------
__global__ __launch_bounds__(128) void scan2_kernel(
    const float* __restrict__ A_log, const float* __restrict__ delta_b)
{
    __shared__ float sG[L_], sU[L_], sC[L_];
    __shared__ float sA[128], sB[128];
    const int b = blockIdx.x >> 4, s = blockIdx.x & 15;
    const int tid = threadIdx.x;

    const float Aval = -expf(A_log[s]);
    const float dbias = delta_b[s];
    const float* d0 = g_dots;
    const float* d1 = g_dots + (size_t)M_ * NC_;

    for (int l = tid; l < L_; l += 128) {
        size_t ro = (size_t)(b * L_ + l) * NC_;
        float dd = d0[ro + s]      + d1[ro + s];
        float db = d0[ro + 16 + s] + d1[ro + 16 + s];
        float dc = d0[ro + 32 + s] + d1[ro + 32 + s];
        float rs = d0[ro + 48]     + d1[ro + 48];
        float z = dd + dbias;
        float delta = (z > 20.f) ? z : log1pf(expf(z));
        sG[l] = expf(delta * Aval);
        sU[l] = delta * db * (rs * (1.f / (float)DI_));
        sC[l] = dc;
    }
    __syncthreads();

    const int CH = L_ / 128;   // 16
    const int l0 = tid * CH;
    float A = 1.f, U = 0.f;
    #pragma unroll
    for (int i = 0; i < CH; i++) {
        float gv = sG[l0 + i];
        A *= gv;
        U = fmaf(gv, U, sU[l0 + i]);
    }
    sA[tid] = A; sB[tid] = U;
    __syncthreads();

    #pragma unroll
    for (int d = 1; d < 128; d <<= 1) {
        float a2 = sA[tid], u2 = sB[tid];
        float a1 = 1.f, u1 = 0.f;
        if (tid >= d) { a1 = sA[tid - d]; u1 = sB[tid - d]; }
        __syncthreads();
        sA[tid] = a2 * a1;
        sB[tid] = fmaf(a2, u1, u2);
        __syncthreads();
    }

    float h = (tid == 0) ? 0.f : sB[tid - 1];
    #pragma unroll
    for (int i = 0; i < CH; i++) {
        h = fmaf(sG[l0 + i], h, sU[l0 + i]);
        sU[l0 + i] = h * sC[l0 + i];
    }
    __syncthreads();
    const size_t base = (size_t)s * M_ + (size_t)b * L_;
    for (int i = tid; i < L_ / 4; i += 128)
        *(float4*)(g_hc + base + i * 4) = ((float4*)sU)[i];
}

// ---------------- yskip (fused ysum): one 512-thread block per row ----------
__global__ __launch_bounds__(512) void yskip_kernel(const float* __restrict__ Dp)
{
    __shared__ float ysh;
    const int r = blockIdx.x;
    const int tid = threadIdx.x;

    if (tid < 16) {
        float v = g_hc[(size_t)tid * M_ + r];
        #pragma unroll
        for (int o = 8; o >= 1; o >>= 1)
            v += __shfl_xor_sync(0x0000ffffu, v, o);
        if (tid == 0) ysh = v;
    }
    __syncthreads();
    float yv = ysh;

    int i = tid * 4;
    uint2 graw = *(const uint2*)(g_xinner + (size_t)r * N1_ + DI_ + i);
    float2 g0 = __half22float2(*(__half2*)&graw.x);
    float2 g1 = __half22float2(*(__half2*)&graw.y);
    uint2 xraw = ((const uint2*)g_xc16)[(size_t)r * (DI_ / 4) + tid];
    float2 x0 = __half22float2(*(__half2*)&xraw.x);
    float2 x1 = __half22float2(*(__half2*)&xraw.y);
    float4 dv = *(const float4*)(Dp + i);
    float f0 = fmaf(yv, g0.x * fast_sigmoid(g0.x), x0.x * dv.x);
    float f1 = fmaf(yv, g0.y * fast_sigmoid(g0.y), x0.y * dv.y);
    float f2 = fmaf(yv, g1.x * fast_sigmoid(g1.x), x1.x * dv.z);
    float f3 = fmaf(yv, g1.y * fast_sigmoid(g1.y), x1.y * dv.w);
    __half2 a = __floats2half2_rn(f0, f1);
    __half2 b = __floats2half2_rn(f2, f3);
    ((uint2*)g_ys)[(size_t)r * (DI_ / 4) + tid] = make_uint2(*(uint32_t*)&a, *(uint32_t*)&b);
}

// ---------------- launch ----------------
extern "C" void kernel_launch(void* const* d_in, const int* in_sizes, int n_in,
                              void* d_out, int out_size)
{
    const float* x          = (const float*)d_in[0];
    const float* in_proj_w  = (const float*)d_in[1];
    const float* conv_w     = (const float*)d_in[2];
    const float* conv_b     = (const float*)d_in[3];
    const float* A_log      = (const float*)d_in[4];
    const float* Dp         = (const float*)d_in[5];
    const float* delta_w    = (const float*)d_in[6];
    const float* delta_b    = (const float*)d_in[7];
    const float* B_w        = (const float*)d_in[8];
    const float* C_w        = (const float*)d_in[9];
    const float* out_proj_w = (const float*)d_in[10];
    float* out = (float*)d_out;

    __half *p_xinner, *p_xf, *p_w1, *p_wo, *p_wc, *p_ys;
    float *p_dots;
    cudaGetSymbolAddress((void**)&p_xinner, g_xinner);
    cudaGetSymbolAddress((void**)&p_xf, g_xf);
    cudaGetSymbolAddress((void**)&p_w1, g_w1);
    cudaGetSymbolAddress((void**)&p_wo, g_wo);
    cudaGetSymbolAddress((void**)&p_wc, g_wc);
    cudaGetSymbolAddress((void**)&p_ys, g_ys);
    cudaGetSymbolAddress((void**)&p_dots, g_dots);

    cudaFuncSetAttribute(gemm_tc<__half>, cudaFuncAttributeMaxDynamicSharedMemorySize, SMEM_TOTAL);
    cudaFuncSetAttribute(gemm_tc<float>,  cudaFuncAttributeMaxDynamicSharedMemorySize, SMEM_TOTAL);
    cudaFuncSetAttribute(convdbc_kernel,  cudaFuncAttributeMaxDynamicSharedMemorySize, CD_SMEM);

    // 0) all prep in one kernel
    prep_all_kernel<<<NB_X + NB_W1 + NB_WO + NB_WC, 256>>>(
        x, in_proj_w, out_proj_w, delta_w, B_w, C_w);

    // 1) x_inner = x @ in_proj_w^T  [8192,4096]  (fp16 out)
    gemm_tc<__half><<<dim3(N1_ / BN, M_ / BM, 1), 256, SMEM_TOTAL>>>(
        p_xf, p_w1, p_xinner, M_, N1_, DM_, DM_);

    // 2) fused conv+silu + dots GEMM  (also materializes x_conv fp16)
    convdbc_kernel<<<dim3(1, M_ / 64, KZ_), 256, CD_SMEM>>>(
        p_wc, conv_w, conv_b, p_dots, DI_ / KZ_);

    // 3) scan (coefficient computation fused)
    scan2_kernel<<<B_ * DS_, 128>>>(A_log, delta_b);

    // 4) gate + skip fuse (ysum inlined) -> fp16
    yskip_kernel<<<M_, 512>>>(Dp);

    // 5) out = y_skip @ out_proj_w^T  [8192,1024]  (fp32 out)
    gemm_tc<float><<<dim3(DM_ / BN, M_ / BM, 1), 256, SMEM_TOTAL>>>(
        p_ys, p_wo, out, M_, DM_, DI_, DI_);
}